// round 2
// baseline (speedup 1.0000x reference)
#include <cuda_runtime.h>
#include <math.h>

#define EPS 1e-8f
// sqrt(EPS/2)
#define CEPS 7.0710678e-05f

// ---------------- device scratch (no allocs allowed) ----------------
__device__ float g_M[4 * 512 * 128];        // [s = sqrt(p) | ceps/sqrt(p)]
__device__ float g_W[4 * 512 * 512];        // exp(-2 acos(inner)) (unnormalized)
__device__ float g_X1[4 * 512 * 64];        // intermediate x after iter 1
__device__ float g_gramP[4 * 8 * 64 * 64];  // partial Gram per 64-row chunk
__device__ float g_meanP[4 * 8 * 64];       // partial column sums
__device__ float g_norm[4 * 512];           // per-row L2 norms

// ---------------- K1: p -> M ----------------
// one warp per (b,t) row; lane handles dims {lane, lane+32}
__global__ __launch_bounds__(32) void k_prep(const float* __restrict__ xext) {
    const float* x = xext ? xext : g_X1;
    int row  = blockIdx.x;      // 0..2047
    int lane = threadIdx.x;     // 0..31
    const float* xr = x + row * 64;
    float v0 = xr[lane], v1 = xr[lane + 32];
    // softplus = max(x,0) + log1p(exp(-|x|))
    float sp0 = fmaxf(v0, 0.f) + log1pf(__expf(-fabsf(v0)));
    float sp1 = fmaxf(v1, 0.f) + log1pf(__expf(-fabsf(v1)));
    float s = sp0 + sp1;
    #pragma unroll
    for (int o = 16; o > 0; o >>= 1) s += __shfl_xor_sync(0xffffffff, s, o);
    float inv1 = 1.f / (s + EPS);
    float p0 = fmaxf(sp0 * inv1, EPS);
    float p1 = fmaxf(sp1 * inv1, EPS);
    float s2 = p0 + p1;
    #pragma unroll
    for (int o = 16; o > 0; o >>= 1) s2 += __shfl_xor_sync(0xffffffff, s2, o);
    float inv2 = 1.f / (s2 + EPS);
    p0 *= inv2; p1 *= inv2;
    float q0 = sqrtf(p0), q1 = sqrtf(p1);
    float* Mr = g_M + row * 128;
    Mr[lane]      = q0;
    Mr[lane + 32] = q1;
    Mr[64 + lane]      = CEPS / q0;
    Mr[96 + lane]      = CEPS / q1;
}

// ---------------- K2: W = exp(-2 acos(clip(M M^T))) ----------------
// 64x64 tile per block, 256 threads, 4x4 register micro-tile, K=128.
// Symmetric: only tiles tj<=ti computed, mirrored on store.
__global__ __launch_bounds__(256) void k_qfi() {
    int tj = blockIdx.x, ti = blockIdx.y, b = blockIdx.z;
    if (tj > ti) return;
    const float* A = g_M + b * 512 * 128;
    __shared__ float As[64][33];
    __shared__ float Bs[64][33];
    int tid = threadIdx.x;
    int tx = tid & 15, ty = tid >> 4;
    float acc[4][4] = {};
    for (int kc = 0; kc < 128; kc += 32) {
        for (int l = tid; l < 64 * 32; l += 256) {
            int r = l >> 5, c = l & 31;
            As[r][c] = A[(ti * 64 + r) * 128 + kc + c];
            Bs[r][c] = A[(tj * 64 + r) * 128 + kc + c];
        }
        __syncthreads();
        #pragma unroll
        for (int k = 0; k < 32; k++) {
            float a[4], bb[4];
            #pragma unroll
            for (int u = 0; u < 4; u++) { a[u] = As[ty * 4 + u][k]; bb[u] = Bs[tx * 4 + u][k]; }
            #pragma unroll
            for (int u = 0; u < 4; u++)
                #pragma unroll
                for (int v = 0; v < 4; v++)
                    acc[u][v] = fmaf(a[u], bb[v], acc[u][v]);
        }
        __syncthreads();
    }
    float* Wb = g_W + b * 512 * 512;
    #pragma unroll
    for (int u = 0; u < 4; u++) {
        int i = ti * 64 + ty * 4 + u;
        #pragma unroll
        for (int v = 0; v < 4; v++) {
            int j = tj * 64 + tx * 4 + v;
            float inner = fminf(fmaxf(acc[u][v], -1.f + 1e-6f), 1.f - 1e-6f);
            float w = __expf(-2.f * acosf(inner));
            Wb[i * 512 + j] = w;
            Wb[j * 512 + i] = w;
        }
    }
}

// ---------------- K3: x' = a*x + c*(W x)/rowsum(W) ----------------
// block = 512 threads = 8 rows x 64 dims of one batch
__global__ __launch_bounds__(512) void k_attn(const float* __restrict__ xin_ext,
                                              float* __restrict__ xout_ext,
                                              const float* __restrict__ rsp) {
    const float* xin  = xin_ext  ? xin_ext  : g_X1;
    float*       xout = xout_ext ? xout_ext : g_X1;
    int b = blockIdx.y, rt = blockIdx.x;
    int tid = threadIdx.x;
    int r = tid >> 6, d = tid & 63;
    int row = rt * 8 + r;
    const float* Wb = g_W + b * 512 * 512;
    const float* xb = xin + b * 512 * 64;
    __shared__ float xs[64][64];
    __shared__ float Ws[8][64];
    float acc = 0.f, wsum = 0.f;
    for (int jc = 0; jc < 512; jc += 64) {
        Ws[r][d] = Wb[row * 512 + jc + d];
        for (int l = tid; l < 4096; l += 512) {
            int jj = l >> 6, dd = l & 63;
            xs[jj][dd] = xb[(jc + jj) * 64 + dd];
        }
        __syncthreads();
        #pragma unroll
        for (int j = 0; j < 64; j++) {
            float w = Ws[r][j];
            wsum += w;
            acc = fmaf(w, xs[j][d], acc);
        }
        __syncthreads();
    }
    float q = 0.01f * rsp[0];
    float a = 0.5f * (1.f - q), c = 0.5f * (1.f + q);
    xout[b * 32768 + row * 64 + d] = a * xb[row * 64 + d] + c * (acc / wsum);
}

// ---------------- K4a: partial Gram / mean / norms per 64-row chunk ----------------
__global__ __launch_bounds__(256) void k_stats(const float* __restrict__ x) {
    int b = blockIdx.y, c = blockIdx.x;   // c = 0..7 chunk
    __shared__ float xs[64][68];
    int tid = threadIdx.x;                // 256
    for (int l = tid; l < 4096; l += 256) {
        int t = l >> 6, d = l & 63;
        xs[t][d] = x[b * 32768 + (c * 64 + t) * 64 + d];
    }
    __syncthreads();
    int tx = tid & 15, ty = tid >> 4;
    float acc[4][4] = {};
    #pragma unroll 4
    for (int t = 0; t < 64; t++) {
        float a0[4], b0[4];
        #pragma unroll
        for (int u = 0; u < 4; u++) { a0[u] = xs[t][ty * 4 + u]; b0[u] = xs[t][tx * 4 + u]; }
        #pragma unroll
        for (int u = 0; u < 4; u++)
            #pragma unroll
            for (int v = 0; v < 4; v++)
                acc[u][v] = fmaf(a0[u], b0[v], acc[u][v]);
    }
    float* gp = g_gramP + (b * 8 + c) * 4096;
    #pragma unroll
    for (int u = 0; u < 4; u++)
        #pragma unroll
        for (int v = 0; v < 4; v++)
            gp[(ty * 4 + u) * 64 + tx * 4 + v] = acc[u][v];
    if (tid < 64) {
        float m = 0.f;
        for (int t = 0; t < 64; t++) m += xs[t][tid];
        g_meanP[(b * 8 + c) * 64 + tid] = m;
    } else if (tid < 128) {
        int t = tid - 64;
        float n = 0.f;
        for (int d = 0; d < 64; d++) n = fmaf(xs[t][d], xs[t][d], n);
        g_norm[b * 512 + c * 64 + t] = sqrtf(n);
    }
}

// ---------------- K4b: finalize phi / kappa per batch ----------------
__global__ __launch_bounds__(256) void k_fin(float* __restrict__ out) {
    int b = blockIdx.x;
    int tid = threadIdx.x;   // 256
    __shared__ float mean[64], var[64], red[256];
    if (tid < 64) {
        float g = 0.f, mn = 0.f;
        for (int c = 0; c < 8; c++) {
            g  += g_gramP[(b * 8 + c) * 4096 + tid * 65];
            mn += g_meanP[(b * 8 + c) * 64 + tid];
        }
        float m = mn * (1.f / 512.f);
        float cov = (g - 512.f * m * m) * (1.f / 512.f);
        mean[tid] = m;
        var[tid]  = fmaxf(cov, EPS);
    }
    __syncthreads();
    float local = 0.f;
    for (int k = 0; k < 16; k++) {
        int pid = tid + k * 256;
        int d = pid >> 6, e = pid & 63;
        if (d != e) {
            float g = 0.f;
            for (int c = 0; c < 8; c++) g += g_gramP[(b * 8 + c) * 4096 + pid];
            float cov   = (g - 512.f * mean[d] * mean[e]) * (1.f / 512.f);
            float denom = fmaxf(sqrtf(var[d] * var[e]), EPS);
            float corr  = fminf(fmaxf(cov / denom, -1.f), 1.f);
            local += fabsf(corr);
        }
    }
    float nk = g_norm[b * 512 + tid] + g_norm[b * 512 + 256 + tid];
    red[tid] = local; __syncthreads();
    for (int s = 128; s > 0; s >>= 1) { if (tid < s) red[tid] += red[tid + s]; __syncthreads(); }
    if (tid == 0) out[131072 + b] = red[0] * (1.f / 4096.f);
    __syncthreads();
    red[tid] = nk; __syncthreads();
    for (int s = 128; s > 0; s >>= 1) { if (tid < s) red[tid] += red[tid + s]; __syncthreads(); }
    if (tid == 0) out[131076 + b] = red[0] * (1.f / 512.f);
}

// ---------------- launch ----------------
extern "C" void kernel_launch(void* const* d_in, const int* in_sizes, int n_in,
                              void* d_out, int out_size) {
    const float* basin = (const float*)d_in[0];
    const float* rs    = (const float*)d_in[1];
    if (n_in >= 2 && in_sizes[0] == 1) {  // defensive: scalar first
        basin = (const float*)d_in[1];
        rs    = (const float*)d_in[0];
    }
    float* out = (float*)d_out;

    dim3 gq(8, 8, 4);      // k_qfi tiles (tj, ti, b)
    dim3 ga(64, 4);        // k_attn (row-tile, b)
    dim3 gs(8, 4);         // k_stats (chunk, b)

    // iteration 1: basin -> g_X1
    k_prep<<<2048, 32>>>(basin);
    k_qfi <<<gq, 256>>>();
    k_attn<<<ga, 512>>>(basin, nullptr, rs);

    // iteration 2: g_X1 -> d_out[0 .. 131072)
    k_prep<<<2048, 32>>>(nullptr);
    k_qfi <<<gq, 256>>>();
    k_attn<<<ga, 512>>>(nullptr, out, rs);

    // stats on final x (in d_out)
    k_stats<<<gs, 256>>>(out);
    k_fin  <<<4, 256>>>(out);
}

// round 4
// speedup vs baseline: 1.4020x; 1.4020x over previous
#include <cuda_runtime.h>
#include <math.h>

#define EPS 1e-8f
// sqrt(EPS/2)
#define CEPS 7.0710678e-05f

// ---------------- device scratch (no allocs allowed) ----------------
__device__ float g_M[4 * 512 * 128];        // [sqrt(p) | ceps/sqrt(p)] per row
__device__ float g_acc[4 * 512 * 64];       // x_attn numerator accumulators
__device__ float g_wsum[4 * 512];           // row sums of W
__device__ float g_X1[4 * 512 * 64];        // x after iter 1
__device__ float g_gramP[4 * 8 * 64 * 64];  // partial Gram per 64-row chunk
__device__ float g_meanP[4 * 8 * 64];       // partial column sums
__device__ float g_norm[4 * 512];           // per-row L2 norms

// lower-triangular tile enumeration (36 pairs of 8x8 tile grid)
__device__ __constant__ int c_ti[36] =
    {0,1,1,2,2,2,3,3,3,3,4,4,4,4,4,5,5,5,5,5,5,6,6,6,6,6,6,6,7,7,7,7,7,7,7,7};
__device__ __constant__ int c_tj[36] =
    {0,0,1,0,1,2,0,1,2,3,0,1,2,3,4,0,1,2,3,4,5,0,1,2,3,4,5,6,0,1,2,3,4,5,6,7};

// ---------------- K1: basin -> M, zero accumulators ----------------
// 512 threads = 8 rows x 64 dims; grid 256
__global__ __launch_bounds__(512) void k_prep(const float* __restrict__ x) {
    int tid = threadIdx.x;
    int r = tid >> 6, d = tid & 63;
    int g = blockIdx.x * 8 + r;           // global row 0..2047
    float v = x[g * 64 + d];
    float sp = fmaxf(v, 0.f) + log1pf(__expf(-fabsf(v)));
    __shared__ float part[8][2];
    float s = sp;
    #pragma unroll
    for (int o = 16; o > 0; o >>= 1) s += __shfl_xor_sync(0xffffffff, s, o);
    if ((d & 31) == 0) part[r][d >> 5] = s;
    __syncthreads();
    float tot = part[r][0] + part[r][1];
    float p = fmaxf(sp / (tot + EPS), EPS);
    __syncthreads();
    float s2 = p;
    #pragma unroll
    for (int o = 16; o > 0; o >>= 1) s2 += __shfl_xor_sync(0xffffffff, s2, o);
    if ((d & 31) == 0) part[r][d >> 5] = s2;
    __syncthreads();
    float tot2 = part[r][0] + part[r][1];
    p /= (tot2 + EPS);
    float sq = sqrtf(p);
    g_M[g * 128 + d] = sq;
    g_M[g * 128 + 64 + d] = CEPS / sq;
    g_acc[g * 64 + d] = 0.f;
    if (d == 0) g_wsum[g] = 0.f;
}

// ---------------- K2: fused QFI attention block ----------------
// grid (36, 4), 256 threads. Block (ti,tj,b):
//   GEMM1: inner = M_i . M_j (64x64x128), epilogue -> w
//   GEMM2a: acc[i-tile] += w @ x[j-tile]   (+ rowsum(w) -> wsum[i])
//   GEMM2b: acc[j-tile] += w^T @ x[i-tile] (+ colsum(w) -> wsum[j])  [off-diag]
__global__ __launch_bounds__(256) void k_fused(const float* __restrict__ xin_ext) {
    __shared__ float sbuf[12288];   // 48KB, phase-unioned
    int pi = blockIdx.x, b = blockIdx.y;
    int ti = c_ti[pi], tj = c_tj[pi];
    const float* xin = xin_ext ? xin_ext : g_X1;
    const float* A  = g_M + b * 512 * 128;
    const float* xb = xin + b * 32768;
    int tid = threadIdx.x;
    int tx = tid & 15, ty = tid >> 4;

    // ---- GEMM1 ----
    float (*As)[33] = (float(*)[33])sbuf;
    float (*Bs)[33] = (float(*)[33])(sbuf + 64 * 33);
    float acc[4][4] = {};
    for (int kc = 0; kc < 128; kc += 32) {
        for (int l = tid; l < 2048; l += 256) {
            int r = l >> 5, c = l & 31;
            As[r][c] = A[(ti * 64 + r) * 128 + kc + c];
            Bs[r][c] = A[(tj * 64 + r) * 128 + kc + c];
        }
        __syncthreads();
        #pragma unroll
        for (int k = 0; k < 32; k++) {
            float a[4], bb[4];
            #pragma unroll
            for (int u = 0; u < 4; u++) { a[u] = As[ty * 4 + u][k]; bb[u] = Bs[tx * 4 + u][k]; }
            #pragma unroll
            for (int u = 0; u < 4; u++)
                #pragma unroll
                for (int v = 0; v < 4; v++)
                    acc[u][v] = fmaf(a[u], bb[v], acc[u][v]);
        }
        __syncthreads();
    }

    // ---- epilogue: w = exp(-2 acos(clip(inner))), stash in smem ----
    float (*wS)[64]  = (float(*)[64])sbuf;          // rows i, cols j
    float (*xjS)[64] = (float(*)[64])(sbuf + 4096); // x of j-tile
    float (*xiS)[64] = (float(*)[64])(sbuf + 8192); // x of i-tile
    float w[4][4];
    float rsum[4];
    #pragma unroll
    for (int u = 0; u < 4; u++) {
        rsum[u] = 0.f;
        #pragma unroll
        for (int v = 0; v < 4; v++) {
            float inner = fminf(fmaxf(acc[u][v], -1.f + 1e-6f), 1.f - 1e-6f);
            float ww = __expf(-2.f * acosf(inner));
            w[u][v] = ww;
            rsum[u] += ww;
        }
        // reduce over tx (lanes xor 1,2,4,8 within half-warp)
        #pragma unroll
        for (int o = 8; o > 0; o >>= 1) rsum[u] += __shfl_xor_sync(0xffffffff, rsum[u], o);
    }
    // store w tile (STS.128 per row)
    #pragma unroll
    for (int u = 0; u < 4; u++) {
        float4 wv = make_float4(w[u][0], w[u][1], w[u][2], w[u][3]);
        *(float4*)&wS[ty * 4 + u][tx * 4] = wv;
    }
    if (tx == 0) {
        #pragma unroll
        for (int u = 0; u < 4; u++)
            atomicAdd(&g_wsum[b * 512 + ti * 64 + ty * 4 + u], rsum[u]);
    }
    // load x tiles
    for (int l = tid; l < 4096; l += 256) {
        int r = l >> 6, c = l & 63;
        xjS[r][c] = xb[(tj * 64 + r) * 64 + c];
    }
    if (ti != tj) {
        for (int l = tid; l < 4096; l += 256) {
            int r = l >> 6, c = l & 63;
            xiS[r][c] = xb[(ti * 64 + r) * 64 + c];
        }
    }
    __syncthreads();

    // column sums -> wsum[j-tile] (mirror rows), off-diag only
    if (ti != tj && tid < 64) {
        float cs = 0.f;
        #pragma unroll 8
        for (int i = 0; i < 64; i++) cs += wS[i][tid];
        atomicAdd(&g_wsum[b * 512 + tj * 64 + tid], cs);
    }

    float* accb = g_acc + b * 32768;

    // ---- GEMM2a: acc[i-tile] += w @ x_j ----
    {
        float o1[4][4] = {};
        #pragma unroll 4
        for (int k = 0; k < 64; k++) {
            float4 bv = *(const float4*)&xjS[k][tx * 4];
            #pragma unroll
            for (int u = 0; u < 4; u++) {
                float a_ = wS[ty * 4 + u][k];
                o1[u][0] = fmaf(a_, bv.x, o1[u][0]);
                o1[u][1] = fmaf(a_, bv.y, o1[u][1]);
                o1[u][2] = fmaf(a_, bv.z, o1[u][2]);
                o1[u][3] = fmaf(a_, bv.w, o1[u][3]);
            }
        }
        #pragma unroll
        for (int u = 0; u < 4; u++) {
            float* dst = accb + (ti * 64 + ty * 4 + u) * 64 + tx * 4;
            atomicAdd(dst + 0, o1[u][0]);
            atomicAdd(dst + 1, o1[u][1]);
            atomicAdd(dst + 2, o1[u][2]);
            atomicAdd(dst + 3, o1[u][3]);
        }
    }

    // ---- GEMM2b: acc[j-tile] += w^T @ x_i ---- (off-diag only)
    if (ti != tj) {
        float o2[4][4] = {};
        #pragma unroll 4
        for (int k = 0; k < 64; k++) {
            float4 av = *(const float4*)&wS[k][ty * 4];
            float4 bv = *(const float4*)&xiS[k][tx * 4];
            float aa[4] = {av.x, av.y, av.z, av.w};
            #pragma unroll
            for (int u = 0; u < 4; u++) {
                o2[u][0] = fmaf(aa[u], bv.x, o2[u][0]);
                o2[u][1] = fmaf(aa[u], bv.y, o2[u][1]);
                o2[u][2] = fmaf(aa[u], bv.z, o2[u][2]);
                o2[u][3] = fmaf(aa[u], bv.w, o2[u][3]);
            }
        }
        #pragma unroll
        for (int u = 0; u < 4; u++) {
            float* dst = accb + (tj * 64 + ty * 4 + u) * 64 + tx * 4;
            atomicAdd(dst + 0, o2[u][0]);
            atomicAdd(dst + 1, o2[u][1]);
            atomicAdd(dst + 2, o2[u][2]);
            atomicAdd(dst + 3, o2[u][3]);
        }
    }
}

// ---------------- K3: blend + (optionally) next-iter M + zero accumulators ----
// 512 threads = 8 rows x 64 dims; grid 256
template<int MAKE_M>
__global__ __launch_bounds__(512) void k_blend(const float* __restrict__ xin_ext,
                                               float* __restrict__ xout_ext,
                                               const float* __restrict__ rsp) {
    const float* xin  = xin_ext  ? xin_ext  : g_X1;
    float*       xout = xout_ext ? xout_ext : g_X1;
    int tid = threadIdx.x;
    int r = tid >> 6, d = tid & 63;
    int g = blockIdx.x * 8 + r;
    float q = 0.01f * rsp[0];
    float a0 = 0.5f * (1.f - q), c0 = 0.5f * (1.f + q);
    float v = a0 * xin[g * 64 + d] + c0 * (g_acc[g * 64 + d] / g_wsum[g]);
    xout[g * 64 + d] = v;
    g_acc[g * 64 + d] = 0.f;
    if (d == 0) g_wsum[g] = 0.f;
    if (MAKE_M) {
        float sp = fmaxf(v, 0.f) + log1pf(__expf(-fabsf(v)));
        __shared__ float part[8][2];
        float s = sp;
        #pragma unroll
        for (int o = 16; o > 0; o >>= 1) s += __shfl_xor_sync(0xffffffff, s, o);
        if ((d & 31) == 0) part[r][d >> 5] = s;
        __syncthreads();
        float tot = part[r][0] + part[r][1];
        float p = fmaxf(sp / (tot + EPS), EPS);
        __syncthreads();
        float s2 = p;
        #pragma unroll
        for (int o = 16; o > 0; o >>= 1) s2 += __shfl_xor_sync(0xffffffff, s2, o);
        if ((d & 31) == 0) part[r][d >> 5] = s2;
        __syncthreads();
        float tot2 = part[r][0] + part[r][1];
        p /= (tot2 + EPS);
        float sq = sqrtf(p);
        g_M[g * 128 + d] = sq;
        g_M[g * 128 + 64 + d] = CEPS / sq;
    }
}

// ---------------- K4a: partial Gram / mean / norms per 64-row chunk ----------------
__global__ __launch_bounds__(256) void k_stats(const float* __restrict__ x) {
    int b = blockIdx.y, c = blockIdx.x;
    __shared__ float xs[64][68];
    int tid = threadIdx.x;
    for (int l = tid; l < 4096; l += 256) {
        int t = l >> 6, d = l & 63;
        xs[t][d] = x[b * 32768 + (c * 64 + t) * 64 + d];
    }
    __syncthreads();
    int tx = tid & 15, ty = tid >> 4;
    float acc[4][4] = {};
    #pragma unroll 4
    for (int t = 0; t < 64; t++) {
        float a0[4], b0[4];
        #pragma unroll
        for (int u = 0; u < 4; u++) { a0[u] = xs[t][ty * 4 + u]; b0[u] = xs[t][tx * 4 + u]; }
        #pragma unroll
        for (int u = 0; u < 4; u++)
            #pragma unroll
            for (int v = 0; v < 4; v++)
                acc[u][v] = fmaf(a0[u], b0[v], acc[u][v]);
    }
    float* gp = g_gramP + (b * 8 + c) * 4096;
    #pragma unroll
    for (int u = 0; u < 4; u++)
        #pragma unroll
        for (int v = 0; v < 4; v++)
            gp[(ty * 4 + u) * 64 + tx * 4 + v] = acc[u][v];
    if (tid < 64) {
        float m = 0.f;
        for (int t = 0; t < 64; t++) m += xs[t][tid];
        g_meanP[(b * 8 + c) * 64 + tid] = m;
    } else if (tid < 128) {
        int t = tid - 64;
        float n = 0.f;
        for (int d = 0; d < 64; d++) n = fmaf(xs[t][d], xs[t][d], n);
        g_norm[b * 512 + c * 64 + t] = sqrtf(n);
    }
}

// ---------------- K4b: finalize phi / kappa per batch ----------------
__global__ __launch_bounds__(256) void k_fin(float* __restrict__ out) {
    int b = blockIdx.x;
    int tid = threadIdx.x;
    __shared__ float mean[64], var[64], red[256];
    if (tid < 64) {
        float g = 0.f, mn = 0.f;
        for (int c = 0; c < 8; c++) {
            g  += g_gramP[(b * 8 + c) * 4096 + tid * 65];
            mn += g_meanP[(b * 8 + c) * 64 + tid];
        }
        float m = mn * (1.f / 512.f);
        float cov = (g - 512.f * m * m) * (1.f / 512.f);
        mean[tid] = m;
        var[tid]  = fmaxf(cov, EPS);
    }
    __syncthreads();
    float local = 0.f;
    for (int k = 0; k < 16; k++) {
        int pid = tid + k * 256;
        int d = pid >> 6, e = pid & 63;
        if (d != e) {
            float g = 0.f;
            for (int c = 0; c < 8; c++) g += g_gramP[(b * 8 + c) * 4096 + pid];
            float cov   = (g - 512.f * mean[d] * mean[e]) * (1.f / 512.f);
            float denom = fmaxf(sqrtf(var[d] * var[e]), EPS);
            float corr  = fminf(fmaxf(cov / denom, -1.f), 1.f);
            local += fabsf(corr);
        }
    }
    float nk = g_norm[b * 512 + tid] + g_norm[b * 512 + 256 + tid];
    red[tid] = local; __syncthreads();
    for (int s = 128; s > 0; s >>= 1) { if (tid < s) red[tid] += red[tid + s]; __syncthreads(); }
    if (tid == 0) out[131072 + b] = red[0] * (1.f / 4096.f);
    __syncthreads();
    red[tid] = nk; __syncthreads();
    for (int s = 128; s > 0; s >>= 1) { if (tid < s) red[tid] += red[tid + s]; __syncthreads(); }
    if (tid == 0) out[131076 + b] = red[0] * (1.f / 512.f);
}

// ---------------- launch ----------------
extern "C" void kernel_launch(void* const* d_in, const int* in_sizes, int n_in,
                              void* d_out, int out_size) {
    const float* basin = (const float*)d_in[0];
    const float* rs    = (const float*)d_in[1];
    if (n_in >= 2 && in_sizes[0] == 1) {  // defensive: scalar first
        basin = (const float*)d_in[1];
        rs    = (const float*)d_in[0];
    }
    float* out = (float*)d_out;

    dim3 gf(36, 4);        // k_fused (tri-pair, b)
    dim3 gs(8, 4);         // k_stats (chunk, b)

    // iteration 1: basin -> g_X1 (blend also builds M for iter 2)
    k_prep<<<256, 512>>>(basin);
    k_fused<<<gf, 256>>>(basin);
    k_blend<1><<<256, 512>>>(basin, nullptr, rs);

    // iteration 2: g_X1 -> d_out[0 .. 131072)
    k_fused<<<gf, 256>>>(nullptr);
    k_blend<0><<<256, 512>>>(nullptr, out, rs);

    // stats on final x (in d_out)
    k_stats<<<gs, 256>>>(out);
    k_fin  <<<4, 256>>>(out);
}